// round 14
// baseline (speedup 1.0000x reference)
#include <cuda_runtime.h>
#include <cstdint>

#define BATCH 4
#define NPTS  8192
#define KNN   16
#define CIN   64
#define CO    64
#define F3    192
#define CS    20
#define PPT   4
#define NQ    (BATCH * NPTS)

// grid params
#define G     32
#define G3    (G * G * G)
#define HCELL 0.25f
#define HINV  4.0f
#define ORG   (-4.0f)

#define BIGF  3.4e38f
#define FULLM 0xffffffffu

typedef unsigned long long ull;
typedef unsigned int uint;

__device__ int    g_idx[NQ * KNN];
__device__ float  g_feat3[(size_t)NQ * F3];
__device__ float  g_WgT[CO * CO];   // [c][o] = (w_gamma2 @ w_gamma1)^T
__device__ float  g_WtT[3 * CO];    // [c3][o] = (w_theta2 @ w_theta1)^T

// grid scratch
__device__ int    g_cnt[BATCH * G3];
__device__ int    g_cstart[BATCH * (G3 + 1)];
__device__ int    g_ccur[BATCH * G3];
__device__ int    g_cid[BATCH * NPTS];
__device__ float4 g_spt[BATCH * NPTS];   // cell-sorted points {x,y,z,|p|^2}
__device__ int    g_sid[BATCH * NPTS];   // original index of sorted point

// ---------------------------------------------------------------------------
// packed f32x2 helpers (fused kernel)
// ---------------------------------------------------------------------------
__device__ __forceinline__ ull pack2(float f) {
    ull r; uint u = __float_as_uint(f);
    asm("mov.b64 %0, {%1, %1};" : "=l"(r) : "r"(u));
    return r;
}
__device__ __forceinline__ void fma2(ull& acc, ull a, ull b) {
    asm("fma.rn.f32x2 %0, %1, %2, %0;" : "+l"(acc) : "l"(a), "l"(b));
}
__device__ __forceinline__ float f2lo(ull v) { return __uint_as_float((uint)v); }
__device__ __forceinline__ float f2hi(ull v) { return __uint_as_float((uint)(v >> 32)); }

// ---------------------------------------------------------------------------
// Grid build kernels
// ---------------------------------------------------------------------------
__global__ void __launch_bounds__(256) gzero() {
    int i = blockIdx.x * 256 + threadIdx.x;
    if (i < BATCH * G3) g_cnt[i] = 0;
}

__device__ __forceinline__ int cell_of(float x, float y, float z) {
    int cx = min(G - 1, max(0, (int)floorf((x - ORG) * HINV)));
    int cy = min(G - 1, max(0, (int)floorf((y - ORG) * HINV)));
    int cz = min(G - 1, max(0, (int)floorf((z - ORG) * HINV)));
    return (cz * G + cy) * G + cx;
}

__global__ void __launch_bounds__(256) gcount(const float* __restrict__ coords) {
    const int b = blockIdx.y;
    const int n = blockIdx.x * 256 + threadIdx.x;
    const float* cb = coords + (size_t)b * 3 * NPTS;
    float x = cb[n], y = cb[NPTS + n], z = cb[2 * NPTS + n];
    int cid = cell_of(x, y, z);
    g_cid[b * NPTS + n] = cid;
    atomicAdd(&g_cnt[b * G3 + cid], 1);
}

// per-batch exclusive prefix scan over G3 counts (1024 threads x 32 cells)
__global__ void __launch_bounds__(1024) gscan() {
    __shared__ int part[1024];
    const int b = blockIdx.x;
    const int t = threadIdx.x;
    const int base = b * G3 + t * 32;

    int s = 0;
#pragma unroll 8
    for (int i = 0; i < 32; ++i) s += g_cnt[base + i];
    part[t] = s;
    __syncthreads();
    for (int off = 1; off < 1024; off <<= 1) {
        int v = (t >= off) ? part[t - off] : 0;
        __syncthreads();
        part[t] += v;
        __syncthreads();
    }
    int run = part[t] - s;
    const int obase = b * (G3 + 1) + t * 32;
#pragma unroll 8
    for (int i = 0; i < 32; ++i) {
        int c = g_cnt[base + i];
        g_cstart[obase + i] = run;
        g_ccur[base + i] = run;
        run += c;
    }
    if (t == 1023) g_cstart[b * (G3 + 1) + G3] = part[1023];
}

__global__ void __launch_bounds__(256) gfill(const float* __restrict__ coords) {
    const int b = blockIdx.y;
    const int n = blockIdx.x * 256 + threadIdx.x;
    const float* cb = coords + (size_t)b * 3 * NPTS;
    float x = cb[n], y = cb[NPTS + n], z = cb[2 * NPTS + n];
    int cid = g_cid[b * NPTS + n];
    int pos = atomicAdd(&g_ccur[b * G3 + cid], 1);
    float nrm = fmaf(z, z, fmaf(y, y, x * x));
    g_spt[b * NPTS + pos] = make_float4(x, y, z, nrm);
    g_sid[b * NPTS + pos] = n;
}

// ---------------------------------------------------------------------------
// Warp bitonic top-16 machinery
// ---------------------------------------------------------------------------
__device__ __forceinline__ void cmp_swap(float& v, int& i, int j, bool dirUp, int lane) {
    float ov = __shfl_xor_sync(FULLM, v, j);
    int   oi = __shfl_xor_sync(FULLM, i, j);
    bool lower = (lane & j) == 0;
    bool keepMin = (lower == dirUp);
    bool take = keepMin ? (ov < v) : (ov > v);
    if (take) { v = ov; i = oi; }
}

__device__ __forceinline__ void bitonic_sort32(float& v, int& i, int lane) {
#pragma unroll
    for (int k = 2; k <= 32; k <<= 1) {
        bool dirUp = ((lane & k) == 0);
#pragma unroll
        for (int j = k >> 1; j > 0; j >>= 1)
            cmp_swap(v, i, j, dirUp, lane);
    }
}

// top16 ascending in lanes 0..15; merge batch (v,i) into it
__device__ __forceinline__ void merge_batch(float& topv, int& topi, float& thr,
                                            float v, int i, int lane) {
    bitonic_sort32(v, i, lane);          // batch ascending across lanes
    float mv = __shfl_sync(FULLM, v, 31 - lane);   // lanes 16..31 <- batch[15..0] (descending)
    int   mi = __shfl_sync(FULLM, i, 31 - lane);
    float x  = (lane < 16) ? topv : mv;  // ascending(top16) ++ descending(batch16) = bitonic
    int   xi = (lane < 16) ? topi : mi;
#pragma unroll
    for (int j = 16; j > 0; j >>= 1)     // bitonic merge, ascending
        cmp_swap(x, xi, j, true, lane);
    topv = x; topi = xi;
    thr = __shfl_sync(FULLM, topv, 15);
}

// scan candidate range [s,e): 32 lanes in parallel, batch bitonic merge on hits
__device__ __forceinline__ void wscan_range(const float4* __restrict__ sp,
                                            const int* __restrict__ sid,
                                            int s, int e,
                                            float nx, float ny, float nz,
                                            float& topv, int& topi, float& thr, int lane) {
    for (int j0 = s; j0 < e; j0 += 32) {
        int j = j0 + lane;
        float d = BIGF; int id = 0;
        if (j < e) {
            float4 m = sp[j];
            d  = fmaf(nx, m.x, fmaf(ny, m.y, fmaf(nz, m.z, m.w)));
            id = sid[j];
        }
        if (__ballot_sync(FULLM, d < thr))
            merge_batch(topv, topi, thr, d, id, lane);
    }
}

// ---------------------------------------------------------------------------
// Warp-cooperative grid KNN. One warp per query.
// key = |m|^2 - 2 q.m  (same formula as all previous passing kernels)
// ---------------------------------------------------------------------------
__global__ void __launch_bounds__(256) gknn() {
    const int wid  = (blockIdx.x * 256 + threadIdx.x) >> 5;
    const int lane = threadIdx.x & 31;
    const int b  = wid >> 13;
    const int si = wid & (NPTS - 1);
    const float4* sp = g_spt + (size_t)b * NPTS;
    const int*   sid = g_sid + (size_t)b * NPTS;
    const int*   cs  = g_cstart + (size_t)b * (G3 + 1);

    float4 q4 = sp[si];
    const float qn = q4.w;
    const float nx = -2.f * q4.x, ny = -2.f * q4.y, nz = -2.f * q4.z;
    const int cx = min(G - 1, max(0, (int)floorf((q4.x - ORG) * HINV)));
    const int cy = min(G - 1, max(0, (int)floorf((q4.y - ORG) * HINV)));
    const int cz = min(G - 1, max(0, (int)floorf((q4.z - ORG) * HINV)));

    float topv = BIGF; int topi = 0; float thr = BIGF;

    // ---- fused rings 0+1: 3x3x3 block, row ranges fetched lane-parallel ----
    {
        const int zlo = max(cz - 1, 0), zhi = min(cz + 1, G - 1);
        const int ylo = max(cy - 1, 0), yhi = min(cy + 1, G - 1);
        const int xlo = max(cx - 1, 0), xhi = min(cx + 1, G - 1);
        const int ny_ = yhi - ylo + 1;
        const int nrows = (zhi - zlo + 1) * ny_;
        int rs = 0, re = 0;
        if (lane < nrows) {
            int dz = lane / ny_, dy = lane % ny_;
            int rowbase = ((zlo + dz) * G + (ylo + dy)) * G;
            rs = cs[rowbase + xlo];
            re = cs[rowbase + xhi + 1];
        }
        for (int row = 0; row < nrows; ++row) {
            int s = __shfl_sync(FULLM, rs, row);
            int e = __shfl_sync(FULLM, re, row);
            wscan_range(sp, sid, s, e, nx, ny, nz, topv, topi, thr, lane);
        }
    }

    // ---- expanding rings r >= 2 with certified termination ----
    for (int r = 2; r < G; ++r) {
        float rb = (float)(r - 1) * HCELL;
        if (thr + qn <= rb * rb - 1e-3f) break;   // unscanned keys >= rb^2 - qn
        const int zlo = max(cz - r, 0), zhi = min(cz + r, G - 1);
        const int ylo = max(cy - r, 0), yhi = min(cy + r, G - 1);
        const int xlo = max(cx - r, 0), xhi = min(cx + r, G - 1);
        for (int z = zlo; z <= zhi; ++z) {
            const int adz = abs(z - cz);
            for (int y = ylo; y <= yhi; ++y) {
                const int ady = abs(y - cy);
                const int rowbase = (z * G + y) * G;
                if (max(adz, ady) == r) {
                    int s = cs[rowbase + xlo];
                    int e = cs[rowbase + xhi + 1];
                    wscan_range(sp, sid, s, e, nx, ny, nz, topv, topi, thr, lane);
                } else {
                    if (cx - r >= 0) {
                        int c0 = rowbase + cx - r;
                        wscan_range(sp, sid, cs[c0], cs[c0 + 1], nx, ny, nz, topv, topi, thr, lane);
                    }
                    if (cx + r <= G - 1) {
                        int c1 = rowbase + cx + r;
                        wscan_range(sp, sid, cs[c1], cs[c1 + 1], nx, ny, nz, topv, topi, thr, lane);
                    }
                }
            }
        }
    }

    // write 16 indices (order arbitrary: downstream reduces over k)
    const int qorig = sid[si];
    if (lane < KNN)
        g_idx[((size_t)b * NPTS + qorig) * KNN + lane] = topi;
}

// ---------------------------------------------------------------------------
// Kernel W: precombine weights (no ReLU between pairs -> linear fold)
// ---------------------------------------------------------------------------
__global__ void __launch_bounds__(256) wprep(const float* __restrict__ w_theta1,
                                             const float* __restrict__ w_theta2,
                                             const float* __restrict__ w_gamma1,
                                             const float* __restrict__ w_gamma2) {
    __shared__ float s1[4096], s2[4096];
    const int t = threadIdx.x;
    for (int i = t; i < 4096; i += 256) { s1[i] = w_gamma1[i]; s2[i] = w_gamma2[i]; }
    __syncthreads();
    {
        int i = blockIdx.x * 256 + t;
        int c = i >> 6, o = i & 63;
        float a = 0.f;
#pragma unroll 16
        for (int m = 0; m < 64; ++m) a = fmaf(s2[o * 64 + m], s1[m * 64 + c], a);
        g_WgT[c * 64 + o] = a;
    }
    if (blockIdx.x == 0 && t < 192) {
        int c3 = t / 64, o = t % 64;
        float a = 0.f;
#pragma unroll 16
        for (int m = 0; m < 64; ++m) a = fmaf(w_theta2[o * 64 + m], w_theta1[m * 3 + c3], a);
        g_WtT[c3 * 64 + o] = a;
    }
}

// ---------------------------------------------------------------------------
// Kernel 2: feat3[b,n,o] = sum_c w_lin[o,c] * features[b,c,n]
// ---------------------------------------------------------------------------
__global__ void __launch_bounds__(128) feat3_kernel(const float* __restrict__ features,
                                                    const float* __restrict__ w_lin) {
    __shared__ float sw[F3 * CIN];
    for (int i = threadIdx.x; i < F3 * CIN; i += 128) sw[i] = w_lin[i];

    const int b = blockIdx.y;
    const int n = blockIdx.x * 128 + threadIdx.x;

    float f[CIN];
    const float* fb = features + (size_t)b * CIN * NPTS + n;
#pragma unroll
    for (int c = 0; c < CIN; ++c) f[c] = fb[(size_t)c * NPTS];
    __syncthreads();

    float* outp = g_feat3 + ((size_t)b * NPTS + n) * F3;
    const float4* sw4 = (const float4*)sw;
#pragma unroll 1
    for (int og = 0; og < F3 / 4; ++og) {
        float a0 = 0.f, a1 = 0.f, a2 = 0.f, a3 = 0.f;
#pragma unroll
        for (int c4 = 0; c4 < CIN / 4; ++c4) {
            float4 w0 = sw4[(og * 4 + 0) * 16 + c4];
            float4 w1 = sw4[(og * 4 + 1) * 16 + c4];
            float4 w2 = sw4[(og * 4 + 2) * 16 + c4];
            float4 w3 = sw4[(og * 4 + 3) * 16 + c4];
            int c = c4 * 4;
            a0 = fmaf(w0.x, f[c], fmaf(w0.y, f[c+1], fmaf(w0.z, f[c+2], fmaf(w0.w, f[c+3], a0))));
            a1 = fmaf(w1.x, f[c], fmaf(w1.y, f[c+1], fmaf(w1.z, f[c+2], fmaf(w1.w, f[c+3], a1))));
            a2 = fmaf(w2.x, f[c], fmaf(w2.y, f[c+1], fmaf(w2.z, f[c+2], fmaf(w2.w, f[c+3], a2))));
            a3 = fmaf(w3.x, f[c], fmaf(w3.y, f[c+1], fmaf(w3.z, f[c+2], fmaf(w3.w, f[c+3], a3))));
        }
        ((float4*)outp)[og] = make_float4(a0, a1, a2, a3);
    }
}

// ---------------------------------------------------------------------------
__device__ __forceinline__ void gemm64(ull acc[8], const float* __restrict__ wcolT,
                                       const float* __restrict__ vrow) {
#pragma unroll
    for (int p = 0; p < 8; ++p) acc[p] = 0ull;
#pragma unroll 16
    for (int c = 0; c < 64; ++c) {
        float4 w = *(const float4*)(wcolT + c * 64);
        double2 vv = *(const double2*)(vrow + c * CS);
        ull v0 = __double_as_longlong(vv.x);
        ull v1 = __double_as_longlong(vv.y);
        ull w0 = pack2(w.x), w1 = pack2(w.y), w2 = pack2(w.z), w3 = pack2(w.w);
        fma2(acc[0], w0, v0); fma2(acc[1], w0, v1);
        fma2(acc[2], w1, v0); fma2(acc[3], w1, v1);
        fma2(acc[4], w2, v0); fma2(acc[5], w2, v1);
        fma2(acc[6], w3, v0); fma2(acc[7], w3, v1);
    }
}

#define TEAM_BAR() asm volatile("bar.sync %0, 64;" :: "r"(barid) : "memory")

// ---------------------------------------------------------------------------
// Kernel 3: fused attention (proven version: P-loop, grid 2048)
// ---------------------------------------------------------------------------
#define TA 2560
__global__ void __launch_bounds__(256) fused_kernel(const float* __restrict__ coords,
                                                    float* __restrict__ out) {
    extern __shared__ float sm[];
    float* sWgT = sm;            // 4096  [c][o]
    float* sWtT = sm + 4096;     // 192   [c3][o]

    const int tid = threadIdx.x;
    for (int i = tid; i < 4096; i += 256) sWgT[i] = g_WgT[i];
    if (tid < 192) sWtT[tid] = g_WtT[tid];
    __syncthreads();

    const int gq  = tid >> 6;
    const int t64 = tid & 63;
    const int og  = t64 >> 2;
    const int kg  = t64 & 3;
    const int k    = t64 & 15;
    const int half = t64 >> 4;
    const int barid = gq + 1;

    float* ig = sm + 4288 + gq * TA;   // [64][CS]
    float* AG = ig + 1280;             // [64][CS]

    for (int P = blockIdx.x * PPT + gq; P < NQ; P += gridDim.x * PPT) {
        const int b = P >> 13;
        const int n = P & (NPTS - 1);

        // ---- gather + delta + staging ----
        {
            int ik = g_idx[(size_t)P * KNN + k];
            const float* cb = coords + (size_t)b * 3 * NPTS;
            float rx = cb[n]            - cb[ik];
            float ry = cb[NPTS + n]     - cb[NPTS + ik];
            float rz = cb[2 * NPTS + n] - cb[2 * NPTS + ik];

            const float* fb = g_feat3 + (size_t)(b * NPTS + ik) * F3;
            const float* fq = g_feat3 + (size_t)P * F3;
#pragma unroll
            for (int c4 = 0; c4 < 4; ++c4) {
                int c = half * 16 + c4 * 4;
                float4 ph = *(const float4*)(fq + c);
                float4 ps = *(const float4*)(fb + 64 + c);
                float4 al = *(const float4*)(fb + 128 + c);
                float4 w0 = *(const float4*)(sWtT + c);
                float4 w1 = *(const float4*)(sWtT + 64 + c);
                float4 w2 = *(const float4*)(sWtT + 128 + c);
                float d0 = fmaxf(fmaf(w2.x, rz, fmaf(w1.x, ry, w0.x * rx)), 0.f);
                float d1 = fmaxf(fmaf(w2.y, rz, fmaf(w1.y, ry, w0.y * rx)), 0.f);
                float d2 = fmaxf(fmaf(w2.z, rz, fmaf(w1.z, ry, w0.z * rx)), 0.f);
                float d3 = fmaxf(fmaf(w2.w, rz, fmaf(w1.w, ry, w0.w * rx)), 0.f);
                ig[(c + 0) * CS + k] = ph.x - ps.x + d0;
                ig[(c + 1) * CS + k] = ph.y - ps.y + d1;
                ig[(c + 2) * CS + k] = ph.z - ps.z + d2;
                ig[(c + 3) * CS + k] = ph.w - ps.w + d3;
                AG[(c + 0) * CS + k] = al.x + d0;
                AG[(c + 1) * CS + k] = al.y + d1;
                AG[(c + 2) * CS + k] = al.z + d2;
                AG[(c + 3) * CS + k] = al.w + d3;
            }
        }
        TEAM_BAR();

        // ---- g = relu(Wg @ ig); softmax over k; weighted sum ----
        ull acc[8];
        gemm64(acc, sWgT + 4 * og, ig + 4 * kg);
#pragma unroll
        for (int i = 0; i < 4; ++i) {
            float g0 = fmaxf(f2lo(acc[2*i]),   0.f);
            float g1 = fmaxf(f2hi(acc[2*i]),   0.f);
            float g2 = fmaxf(f2lo(acc[2*i+1]), 0.f);
            float g3 = fmaxf(f2hi(acc[2*i+1]), 0.f);
            float m = fmaxf(fmaxf(g0, g1), fmaxf(g2, g3));
            m = fmaxf(m, __shfl_xor_sync(0xffffffffu, m, 1));
            m = fmaxf(m, __shfl_xor_sync(0xffffffffu, m, 2));
            float e0 = __expf(g0 - m), e1 = __expf(g1 - m);
            float e2 = __expf(g2 - m), e3 = __expf(g3 - m);
            float s = (e0 + e1) + (e2 + e3);
            float4 a = *(const float4*)&AG[(4 * og + i) * CS + 4 * kg];
            float num = fmaf(e0, a.x, fmaf(e1, a.y, fmaf(e2, a.z, e3 * a.w)));
            s   += __shfl_xor_sync(0xffffffffu, s, 1);
            num += __shfl_xor_sync(0xffffffffu, num, 1);
            s   += __shfl_xor_sync(0xffffffffu, s, 2);
            num += __shfl_xor_sync(0xffffffffu, num, 2);
            if (kg == 0)
                out[((size_t)b * CO + 4 * og + i) * NPTS + n] = num / s;
        }
        TEAM_BAR();
    }
}

// ---------------------------------------------------------------------------
#define FUSED_SMEM ((4288 + PPT * TA) * sizeof(float))
extern "C" void kernel_launch(void* const* d_in, const int* in_sizes, int n_in,
                              void* d_out, int out_size) {
    const float* features = (const float*)d_in[0];
    const float* coords   = (const float*)d_in[1];
    const float* w_lin    = (const float*)d_in[2];
    const float* w_theta1 = (const float*)d_in[3];
    const float* w_theta2 = (const float*)d_in[4];
    const float* w_gamma1 = (const float*)d_in[5];
    const float* w_gamma2 = (const float*)d_in[6];
    float* out = (float*)d_out;

    static bool attr_set = false;
    if (!attr_set) {
        cudaFuncSetAttribute(fused_kernel, cudaFuncAttributeMaxDynamicSharedMemorySize,
                             FUSED_SMEM);
        attr_set = true;
    }

    // grid build + warp-cooperative knn
    gzero<<<(BATCH * G3) / 256, 256>>>();
    gcount<<<dim3(NPTS / 256, BATCH), 256>>>(coords);
    gscan<<<BATCH, 1024>>>();
    gfill<<<dim3(NPTS / 256, BATCH), 256>>>(coords);
    gknn<<<NQ / 8, 256>>>();

    // independent prep
    wprep<<<16, 256>>>(w_theta1, w_theta2, w_gamma1, w_gamma2);
    feat3_kernel<<<dim3(NPTS / 128, BATCH), 128>>>(features, w_lin);

    // fused attention
    fused_kernel<<<2048, 256, FUSED_SMEM>>>(coords, out);
}

// round 15
// speedup vs baseline: 1.0008x; 1.0008x over previous
#include <cuda_runtime.h>
#include <cstdint>

#define BATCH 4
#define NPTS  8192
#define KNN   16
#define CIN   64
#define CO    64
#define F3    192
#define CS    20
#define PPT   4
#define NQ    (BATCH * NPTS)

// grid params
#define G     32
#define G3    (G * G * G)
#define HCELL 0.25f
#define HINV  4.0f
#define ORG   (-4.0f)

#define BIGF  3.4e38f
#define FULLM 0xffffffffu

typedef unsigned long long ull;
typedef unsigned int uint;

__device__ int    g_idx[NQ * KNN];
__device__ float  g_feat3[(size_t)NQ * F3];
__device__ float  g_WgT[CO * CO];   // [c][o] = (w_gamma2 @ w_gamma1)^T
__device__ float  g_WtT[3 * CO];    // [c3][o] = (w_theta2 @ w_theta1)^T

// grid scratch
__device__ int    g_cnt[BATCH * G3];
__device__ int    g_cstart[BATCH * (G3 + 1)];
__device__ int    g_ccur[BATCH * G3];
__device__ int    g_cid[BATCH * NPTS];
__device__ float4 g_spt[BATCH * NPTS];   // cell-sorted points {x,y,z,|p|^2}
__device__ int    g_sid[BATCH * NPTS];   // original index of sorted point

// ---------------------------------------------------------------------------
// packed f32x2 helpers (fused kernel)
// ---------------------------------------------------------------------------
__device__ __forceinline__ ull pack2(float f) {
    ull r; uint u = __float_as_uint(f);
    asm("mov.b64 %0, {%1, %1};" : "=l"(r) : "r"(u));
    return r;
}
__device__ __forceinline__ void fma2(ull& acc, ull a, ull b) {
    asm("fma.rn.f32x2 %0, %1, %2, %0;" : "+l"(acc) : "l"(a), "l"(b));
}
__device__ __forceinline__ float f2lo(ull v) { return __uint_as_float((uint)v); }
__device__ __forceinline__ float f2hi(ull v) { return __uint_as_float((uint)(v >> 32)); }

// ---------------------------------------------------------------------------
// Grid build kernels
// ---------------------------------------------------------------------------
__global__ void __launch_bounds__(256) gzero() {
    int i = blockIdx.x * 256 + threadIdx.x;
    if (i < BATCH * G3) g_cnt[i] = 0;
}

__device__ __forceinline__ int cell_of(float x, float y, float z) {
    int cx = min(G - 1, max(0, (int)floorf((x - ORG) * HINV)));
    int cy = min(G - 1, max(0, (int)floorf((y - ORG) * HINV)));
    int cz = min(G - 1, max(0, (int)floorf((z - ORG) * HINV)));
    return (cz * G + cy) * G + cx;
}

__global__ void __launch_bounds__(256) gcount(const float* __restrict__ coords) {
    const int b = blockIdx.y;
    const int n = blockIdx.x * 256 + threadIdx.x;
    const float* cb = coords + (size_t)b * 3 * NPTS;
    float x = cb[n], y = cb[NPTS + n], z = cb[2 * NPTS + n];
    int cid = cell_of(x, y, z);
    g_cid[b * NPTS + n] = cid;
    atomicAdd(&g_cnt[b * G3 + cid], 1);
}

// per-batch exclusive prefix scan over G3 counts (1024 threads x 32 cells)
__global__ void __launch_bounds__(1024) gscan() {
    __shared__ int part[1024];
    const int b = blockIdx.x;
    const int t = threadIdx.x;
    const int base = b * G3 + t * 32;

    int s = 0;
#pragma unroll 8
    for (int i = 0; i < 32; ++i) s += g_cnt[base + i];
    part[t] = s;
    __syncthreads();
    for (int off = 1; off < 1024; off <<= 1) {
        int v = (t >= off) ? part[t - off] : 0;
        __syncthreads();
        part[t] += v;
        __syncthreads();
    }
    int run = part[t] - s;
    const int obase = b * (G3 + 1) + t * 32;
#pragma unroll 8
    for (int i = 0; i < 32; ++i) {
        int c = g_cnt[base + i];
        g_cstart[obase + i] = run;
        g_ccur[base + i] = run;
        run += c;
    }
    if (t == 1023) g_cstart[b * (G3 + 1) + G3] = part[1023];
}

__global__ void __launch_bounds__(256) gfill(const float* __restrict__ coords) {
    const int b = blockIdx.y;
    const int n = blockIdx.x * 256 + threadIdx.x;
    const float* cb = coords + (size_t)b * 3 * NPTS;
    float x = cb[n], y = cb[NPTS + n], z = cb[2 * NPTS + n];
    int cid = g_cid[b * NPTS + n];
    int pos = atomicAdd(&g_ccur[b * G3 + cid], 1);
    float nrm = fmaf(z, z, fmaf(y, y, x * x));
    g_spt[b * NPTS + pos] = make_float4(x, y, z, nrm);
    g_sid[b * NPTS + pos] = n;
}

// ---------------------------------------------------------------------------
// Warp bitonic top-16 machinery
// ---------------------------------------------------------------------------
__device__ __forceinline__ void cmp_swap(float& v, int& i, int j, bool dirUp, int lane) {
    float ov = __shfl_xor_sync(FULLM, v, j);
    int   oi = __shfl_xor_sync(FULLM, i, j);
    bool lower = (lane & j) == 0;
    bool keepMin = (lower == dirUp);
    bool take = keepMin ? (ov < v) : (ov > v);
    if (take) { v = ov; i = oi; }
}

__device__ __forceinline__ void bitonic_sort32(float& v, int& i, int lane) {
#pragma unroll
    for (int k = 2; k <= 32; k <<= 1) {
        bool dirUp = ((lane & k) == 0);
#pragma unroll
        for (int j = k >> 1; j > 0; j >>= 1)
            cmp_swap(v, i, j, dirUp, lane);
    }
}

// top16 ascending in lanes 0..15; merge batch (v,i) into it
__device__ __forceinline__ void merge_batch(float& topv, int& topi, float& thr,
                                            float v, int i, int lane) {
    bitonic_sort32(v, i, lane);          // batch ascending across lanes
    float mv = __shfl_sync(FULLM, v, 31 - lane);   // lanes 16..31 <- batch[15..0]
    int   mi = __shfl_sync(FULLM, i, 31 - lane);
    float x  = (lane < 16) ? topv : mv;  // ascending(top16) ++ descending(batch16)
    int   xi = (lane < 16) ? topi : mi;
#pragma unroll
    for (int j = 16; j > 0; j >>= 1)     // bitonic merge, ascending
        cmp_swap(x, xi, j, true, lane);
    topv = x; topi = xi;
    thr = __shfl_sync(FULLM, topv, 15);
}

// scan candidate range [s,e): 32 lanes parallel, batch bitonic merge on hits
__device__ __forceinline__ void wscan_range(const float4* __restrict__ sp,
                                            const int* __restrict__ sid,
                                            int s, int e,
                                            float nx, float ny, float nz,
                                            float& topv, int& topi, float& thr, int lane) {
    for (int j0 = s; j0 < e; j0 += 32) {
        int j = j0 + lane;
        float d = BIGF; int id = 0;
        if (j < e) {
            float4 m = sp[j];
            d  = fmaf(nx, m.x, fmaf(ny, m.y, fmaf(nz, m.z, m.w)));
            id = sid[j];
        }
        if (__ballot_sync(FULLM, d < thr))
            merge_batch(topv, topi, thr, d, id, lane);
    }
}

// axis distance from q to cell slab [idx*h, (idx+1)*h); boundary cells are
// half-infinite outward so clamped outliers stay inside their cell's bound.
__device__ __forceinline__ float slab_dist(float q, int idx) {
    float lo = (idx == 0)     ? -BIGF : ORG + idx * HCELL;
    float hi = (idx == G - 1) ?  BIGF : ORG + (idx + 1) * HCELL;
    return fmaxf(0.f, fmaxf(lo - q, q - hi));
}

// ---------------------------------------------------------------------------
// Warp-cooperative grid KNN with geometric cell culling. One warp per query.
// key = |m|^2 - 2 q.m  (same formula as all previous passing kernels)
// ---------------------------------------------------------------------------
__global__ void __launch_bounds__(256) gknn() {
    const int wid  = (blockIdx.x * 256 + threadIdx.x) >> 5;
    const int lane = threadIdx.x & 31;
    const int b  = wid >> 13;
    const int si = wid & (NPTS - 1);
    const float4* sp = g_spt + (size_t)b * NPTS;
    const int*   sid = g_sid + (size_t)b * NPTS;
    const int*   cs  = g_cstart + (size_t)b * (G3 + 1);

    float4 q4 = sp[si];
    const float qn = q4.w;
    const float nx = -2.f * q4.x, ny = -2.f * q4.y, nz = -2.f * q4.z;
    const int cx = min(G - 1, max(0, (int)floorf((q4.x - ORG) * HINV)));
    const int cy = min(G - 1, max(0, (int)floorf((q4.y - ORG) * HINV)));
    const int cz = min(G - 1, max(0, (int)floorf((q4.z - ORG) * HINV)));

    float topv = BIGF; int topi = 0; float thr = BIGF;

    // ---- fused rings 0+1: 3x3x3 block, row ranges fetched lane-parallel ----
    {
        const int zlo = max(cz - 1, 0), zhi = min(cz + 1, G - 1);
        const int ylo = max(cy - 1, 0), yhi = min(cy + 1, G - 1);
        const int xlo = max(cx - 1, 0), xhi = min(cx + 1, G - 1);
        const int ny_ = yhi - ylo + 1;
        const int nrows = (zhi - zlo + 1) * ny_;
        int rs = 0, re = 0;
        if (lane < nrows) {
            int dz = lane / ny_, dy = lane % ny_;
            int rowbase = ((zlo + dz) * G + (ylo + dy)) * G;
            rs = cs[rowbase + xlo];
            re = cs[rowbase + xhi + 1];
        }
        for (int row = 0; row < nrows; ++row) {
            int s = __shfl_sync(FULLM, rs, row);
            int e = __shfl_sync(FULLM, re, row);
            wscan_range(sp, sid, s, e, nx, ny, nz, topv, topi, thr, lane);
        }
    }

    // ---- expanding rings r >= 2, row/cell culled by geometric lower bound ----
    for (int r = 2; r < G; ++r) {
        float rb = (float)(r - 1) * HCELL;
        if (thr + qn <= rb * rb - 1e-3f) break;   // unscanned keys >= rb^2 - qn
        const int zlo = max(cz - r, 0), zhi = min(cz + r, G - 1);
        const int ylo = max(cy - r, 0), yhi = min(cy + r, G - 1);
        const int xlo = max(cx - r, 0), xhi = min(cx + r, G - 1);
        for (int z = zlo; z <= zhi; ++z) {
            const int adz = abs(z - cz);
            float dzd = slab_dist(q4.z, z);
            float dz2 = dzd * dzd;
            if (dz2 >= thr + qn + 1e-3f) continue;   // whole z-slab too far
            for (int y = ylo; y <= yhi; ++y) {
                const int ady = abs(y - cy);
                float dyd = slab_dist(q4.y, y);
                float rowd2 = dz2 + dyd * dyd;
                float need = thr + qn;               // = current d16^2
                if (rowd2 >= need + 1e-3f) continue; // cull row
                const int rowbase = (z * G + y) * G;
                if (max(adz, ady) == r) {
                    // full x-run on ring r: trim to cells inside the d16 ball
                    float rad = sqrtf(need + 1e-3f - rowd2);
                    int ixlo = max(xlo, (int)floorf((q4.x - rad - ORG) * HINV));
                    int ixhi = min(xhi, (int)floorf((q4.x + rad - ORG) * HINV));
                    if (ixlo > ixhi) continue;
                    int s = cs[rowbase + ixlo];
                    int e = cs[rowbase + ixhi + 1];
                    wscan_range(sp, sid, s, e, nx, ny, nz, topv, topi, thr, lane);
                } else {
                    if (cx - r >= 0) {
                        int ix = cx - r;
                        float dxd = slab_dist(q4.x, ix);
                        if (rowd2 + dxd * dxd < need + 1e-3f) {
                            int c0 = rowbase + ix;
                            wscan_range(sp, sid, cs[c0], cs[c0 + 1], nx, ny, nz,
                                        topv, topi, thr, lane);
                        }
                    }
                    if (cx + r <= G - 1) {
                        int ix = cx + r;
                        float dxd = slab_dist(q4.x, ix);
                        if (rowd2 + dxd * dxd < need + 1e-3f) {
                            int c1 = rowbase + ix;
                            wscan_range(sp, sid, cs[c1], cs[c1 + 1], nx, ny, nz,
                                        topv, topi, thr, lane);
                        }
                    }
                }
            }
        }
    }

    // write 16 indices (order arbitrary: downstream reduces over k)
    const int qorig = sid[si];
    if (lane < KNN)
        g_idx[((size_t)b * NPTS + qorig) * KNN + lane] = topi;
}

// ---------------------------------------------------------------------------
// Kernel W: precombine weights (no ReLU between pairs -> linear fold)
// ---------------------------------------------------------------------------
__global__ void __launch_bounds__(256) wprep(const float* __restrict__ w_theta1,
                                             const float* __restrict__ w_theta2,
                                             const float* __restrict__ w_gamma1,
                                             const float* __restrict__ w_gamma2) {
    __shared__ float s1[4096], s2[4096];
    const int t = threadIdx.x;
    for (int i = t; i < 4096; i += 256) { s1[i] = w_gamma1[i]; s2[i] = w_gamma2[i]; }
    __syncthreads();
    {
        int i = blockIdx.x * 256 + t;
        int c = i >> 6, o = i & 63;
        float a = 0.f;
#pragma unroll 16
        for (int m = 0; m < 64; ++m) a = fmaf(s2[o * 64 + m], s1[m * 64 + c], a);
        g_WgT[c * 64 + o] = a;
    }
    if (blockIdx.x == 0 && t < 192) {
        int c3 = t / 64, o = t % 64;
        float a = 0.f;
#pragma unroll 16
        for (int m = 0; m < 64; ++m) a = fmaf(w_theta2[o * 64 + m], w_theta1[m * 3 + c3], a);
        g_WtT[c3 * 64 + o] = a;
    }
}

// ---------------------------------------------------------------------------
// Kernel 2: feat3[b,n,o] = sum_c w_lin[o,c] * features[b,c,n]
// ---------------------------------------------------------------------------
__global__ void __launch_bounds__(128) feat3_kernel(const float* __restrict__ features,
                                                    const float* __restrict__ w_lin) {
    __shared__ float sw[F3 * CIN];
    for (int i = threadIdx.x; i < F3 * CIN; i += 128) sw[i] = w_lin[i];

    const int b = blockIdx.y;
    const int n = blockIdx.x * 128 + threadIdx.x;

    float f[CIN];
    const float* fb = features + (size_t)b * CIN * NPTS + n;
#pragma unroll
    for (int c = 0; c < CIN; ++c) f[c] = fb[(size_t)c * NPTS];
    __syncthreads();

    float* outp = g_feat3 + ((size_t)b * NPTS + n) * F3;
    const float4* sw4 = (const float4*)sw;
#pragma unroll 1
    for (int og = 0; og < F3 / 4; ++og) {
        float a0 = 0.f, a1 = 0.f, a2 = 0.f, a3 = 0.f;
#pragma unroll
        for (int c4 = 0; c4 < CIN / 4; ++c4) {
            float4 w0 = sw4[(og * 4 + 0) * 16 + c4];
            float4 w1 = sw4[(og * 4 + 1) * 16 + c4];
            float4 w2 = sw4[(og * 4 + 2) * 16 + c4];
            float4 w3 = sw4[(og * 4 + 3) * 16 + c4];
            int c = c4 * 4;
            a0 = fmaf(w0.x, f[c], fmaf(w0.y, f[c+1], fmaf(w0.z, f[c+2], fmaf(w0.w, f[c+3], a0))));
            a1 = fmaf(w1.x, f[c], fmaf(w1.y, f[c+1], fmaf(w1.z, f[c+2], fmaf(w1.w, f[c+3], a1))));
            a2 = fmaf(w2.x, f[c], fmaf(w2.y, f[c+1], fmaf(w2.z, f[c+2], fmaf(w2.w, f[c+3], a2))));
            a3 = fmaf(w3.x, f[c], fmaf(w3.y, f[c+1], fmaf(w3.z, f[c+2], fmaf(w3.w, f[c+3], a3))));
        }
        ((float4*)outp)[og] = make_float4(a0, a1, a2, a3);
    }
}

// ---------------------------------------------------------------------------
__device__ __forceinline__ void gemm64(ull acc[8], const float* __restrict__ wcolT,
                                       const float* __restrict__ vrow) {
#pragma unroll
    for (int p = 0; p < 8; ++p) acc[p] = 0ull;
#pragma unroll 16
    for (int c = 0; c < 64; ++c) {
        float4 w = *(const float4*)(wcolT + c * 64);
        double2 vv = *(const double2*)(vrow + c * CS);
        ull v0 = __double_as_longlong(vv.x);
        ull v1 = __double_as_longlong(vv.y);
        ull w0 = pack2(w.x), w1 = pack2(w.y), w2 = pack2(w.z), w3 = pack2(w.w);
        fma2(acc[0], w0, v0); fma2(acc[1], w0, v1);
        fma2(acc[2], w1, v0); fma2(acc[3], w1, v1);
        fma2(acc[4], w2, v0); fma2(acc[5], w2, v1);
        fma2(acc[6], w3, v0); fma2(acc[7], w3, v1);
    }
}

#define TEAM_BAR() asm volatile("bar.sync %0, 64;" :: "r"(barid) : "memory")

// ---------------------------------------------------------------------------
// Kernel 3: fused attention (proven version: P-loop, grid 2048)
// ---------------------------------------------------------------------------
#define TA 2560
__global__ void __launch_bounds__(256) fused_kernel(const float* __restrict__ coords,
                                                    float* __restrict__ out) {
    extern __shared__ float sm[];
    float* sWgT = sm;            // 4096  [c][o]
    float* sWtT = sm + 4096;     // 192   [c3][o]

    const int tid = threadIdx.x;
    for (int i = tid; i < 4096; i += 256) sWgT[i] = g_WgT[i];
    if (tid < 192) sWtT[tid] = g_WtT[tid];
    __syncthreads();

    const int gq  = tid >> 6;
    const int t64 = tid & 63;
    const int og  = t64 >> 2;
    const int kg  = t64 & 3;
    const int k    = t64 & 15;
    const int half = t64 >> 4;
    const int barid = gq + 1;

    float* ig = sm + 4288 + gq * TA;   // [64][CS]
    float* AG = ig + 1280;             // [64][CS]

    for (int P = blockIdx.x * PPT + gq; P < NQ; P += gridDim.x * PPT) {
        const int b = P >> 13;
        const int n = P & (NPTS - 1);

        // ---- gather + delta + staging ----
        {
            int ik = g_idx[(size_t)P * KNN + k];
            const float* cb = coords + (size_t)b * 3 * NPTS;
            float rx = cb[n]            - cb[ik];
            float ry = cb[NPTS + n]     - cb[NPTS + ik];
            float rz = cb[2 * NPTS + n] - cb[2 * NPTS + ik];

            const float* fb = g_feat3 + (size_t)(b * NPTS + ik) * F3;
            const float* fq = g_feat3 + (size_t)P * F3;
#pragma unroll
            for (int c4 = 0; c4 < 4; ++c4) {
                int c = half * 16 + c4 * 4;
                float4 ph = *(const float4*)(fq + c);
                float4 ps = *(const float4*)(fb + 64 + c);
                float4 al = *(const float4*)(fb + 128 + c);
                float4 w0 = *(const float4*)(sWtT + c);
                float4 w1 = *(const float4*)(sWtT + 64 + c);
                float4 w2 = *(const float4*)(sWtT + 128 + c);
                float d0 = fmaxf(fmaf(w2.x, rz, fmaf(w1.x, ry, w0.x * rx)), 0.f);
                float d1 = fmaxf(fmaf(w2.y, rz, fmaf(w1.y, ry, w0.y * rx)), 0.f);
                float d2 = fmaxf(fmaf(w2.z, rz, fmaf(w1.z, ry, w0.z * rx)), 0.f);
                float d3 = fmaxf(fmaf(w2.w, rz, fmaf(w1.w, ry, w0.w * rx)), 0.f);
                ig[(c + 0) * CS + k] = ph.x - ps.x + d0;
                ig[(c + 1) * CS + k] = ph.y - ps.y + d1;
                ig[(c + 2) * CS + k] = ph.z - ps.z + d2;
                ig[(c + 3) * CS + k] = ph.w - ps.w + d3;
                AG[(c + 0) * CS + k] = al.x + d0;
                AG[(c + 1) * CS + k] = al.y + d1;
                AG[(c + 2) * CS + k] = al.z + d2;
                AG[(c + 3) * CS + k] = al.w + d3;
            }
        }
        TEAM_BAR();

        // ---- g = relu(Wg @ ig); softmax over k; weighted sum ----
        ull acc[8];
        gemm64(acc, sWgT + 4 * og, ig + 4 * kg);
#pragma unroll
        for (int i = 0; i < 4; ++i) {
            float g0 = fmaxf(f2lo(acc[2*i]),   0.f);
            float g1 = fmaxf(f2hi(acc[2*i]),   0.f);
            float g2 = fmaxf(f2lo(acc[2*i+1]), 0.f);
            float g3 = fmaxf(f2hi(acc[2*i+1]), 0.f);
            float m = fmaxf(fmaxf(g0, g1), fmaxf(g2, g3));
            m = fmaxf(m, __shfl_xor_sync(0xffffffffu, m, 1));
            m = fmaxf(m, __shfl_xor_sync(0xffffffffu, m, 2));
            float e0 = __expf(g0 - m), e1 = __expf(g1 - m);
            float e2 = __expf(g2 - m), e3 = __expf(g3 - m);
            float s = (e0 + e1) + (e2 + e3);
            float4 a = *(const float4*)&AG[(4 * og + i) * CS + 4 * kg];
            float num = fmaf(e0, a.x, fmaf(e1, a.y, fmaf(e2, a.z, e3 * a.w)));
            s   += __shfl_xor_sync(0xffffffffu, s, 1);
            num += __shfl_xor_sync(0xffffffffu, num, 1);
            s   += __shfl_xor_sync(0xffffffffu, s, 2);
            num += __shfl_xor_sync(0xffffffffu, num, 2);
            if (kg == 0)
                out[((size_t)b * CO + 4 * og + i) * NPTS + n] = num / s;
        }
        TEAM_BAR();
    }
}

// ---------------------------------------------------------------------------
#define FUSED_SMEM ((4288 + PPT * TA) * sizeof(float))
extern "C" void kernel_launch(void* const* d_in, const int* in_sizes, int n_in,
                              void* d_out, int out_size) {
    const float* features = (const float*)d_in[0];
    const float* coords   = (const float*)d_in[1];
    const float* w_lin    = (const float*)d_in[2];
    const float* w_theta1 = (const float*)d_in[3];
    const float* w_theta2 = (const float*)d_in[4];
    const float* w_gamma1 = (const float*)d_in[5];
    const float* w_gamma2 = (const float*)d_in[6];
    float* out = (float*)d_out;

    static bool attr_set = false;
    if (!attr_set) {
        cudaFuncSetAttribute(fused_kernel, cudaFuncAttributeMaxDynamicSharedMemorySize,
                             FUSED_SMEM);
        attr_set = true;
    }

    // grid build + warp-cooperative knn
    gzero<<<(BATCH * G3) / 256, 256>>>();
    gcount<<<dim3(NPTS / 256, BATCH), 256>>>(coords);
    gscan<<<BATCH, 1024>>>();
    gfill<<<dim3(NPTS / 256, BATCH), 256>>>(coords);
    gknn<<<NQ / 8, 256>>>();

    // independent prep
    wprep<<<16, 256>>>(w_theta1, w_theta2, w_gamma1, w_gamma2);
    feat3_kernel<<<dim3(NPTS / 128, BATCH), 128>>>(features, w_lin);

    // fused attention
    fused_kernel<<<2048, 256, FUSED_SMEM>>>(coords, out);
}